// round 10
// baseline (speedup 1.0000x reference)
#include <cuda_runtime.h>

// E3nnSimpleNodeBlock: out = TensorSquare(feats+msgs), N=131072, MUL=16.
// Round 9: R8 symmetric-triangular algorithm +
//  (1) q112 weights packed as ull2 pairs (72 LDS.128/w instead of 136 LDS.64),
//  (2) coalesced input staging via SMEM (kills 32-wavefront scattered LDG.128),
//  (3) same double-buffered per-w slab (672 u64) + staged float4 output flush.

#define T 128
#define NODES_PER_BLOCK 256
#define NNODES 131072

typedef unsigned long long u64;

// Per-w slab, splatted f32x2, pre-scaled (672 u64 per w):
//   [0,272)   : (q000,q110) per triangular pair -> ull2 at [tri]
//   [272,416) : q112 packed pairs: per v, ceil((v+1)/2) ull2 at P16[v], zero-padded
//   [416,672) : 101 weights W101[u][v] at 416 + u*16 + v
__device__ __align__(16) u64 PW2[16 * 672];

// ---------- f32x2 helpers ----------
__device__ __forceinline__ u64 f2fma(u64 a, u64 b, u64 c) {
    u64 d;
    asm("fma.rn.f32x2 %0, %1, %2, %3;" : "=l"(d) : "l"(a), "l"(b), "l"(c));
    return d;
}
__device__ __forceinline__ u64 f2add(u64 a, u64 b) {
    u64 d;
    asm("add.rn.f32x2 %0, %1, %2;" : "=l"(d) : "l"(a), "l"(b));
    return d;
}
__device__ __forceinline__ u64 f2mul(u64 a, u64 b) {
    u64 d;
    asm("mul.rn.f32x2 %0, %1, %2;" : "=l"(d) : "l"(a), "l"(b));
    return d;
}
__device__ __forceinline__ u64 fpack(float lo, float hi) {
    u64 d;
    asm("mov.b64 %0, {%1, %2};" : "=l"(d) : "f"(lo), "f"(hi));
    return d;
}
__device__ __forceinline__ void funpack(u64 p, float& lo, float& hi) {
    asm("mov.b64 {%0, %1}, %2;" : "=f"(lo), "=f"(hi) : "l"(p));
}

// ---------- weight prep ----------
__global__ void prep_kernel(const float* __restrict__ w000, const float* __restrict__ w101,
                            const float* __restrict__ w110, const float* __restrict__ w112) {
    int idx = blockIdx.x * blockDim.x + threadIdx.x;   // 0 .. 16*672-1
    if (idx >= 16 * 672) return;
    int w = idx / 672;
    int slot = idx - w * 672;
    const float A000 = 0.04419417382415922f;           // sqrt(1/(2*MUL*MUL))
    const float A110 = 0.02551551815399144f;           // A000/sqrt(3)
    const float A101 = 0.0625f;                        // sqrt(3/MUL^2)/sqrt(3)
    const float A112 = 0.13975424859373686f;           // sqrt(5)/16

    float val = 0.0f;
    if (slot < 272) {
        int tri = slot >> 1, comp = slot & 1;          // 0 -> q000, 1 -> q110
        int v = 0;
        while ((v + 1) * (v + 2) / 2 <= tri) v++;
        int u = tri - v * (v + 1) / 2;
        const float* src = comp ? w110 : w000;
        float A = comp ? A110 : A000;
        int iuv = u * 256 + v * 16 + w, ivu = v * 256 + u * 16 + w;
        val = (u == v) ? A * src[iuv] : A * (src[iuv] + src[ivu]);
    } else if (slot < 416) {
        int j = slot - 272;                            // u64 index in q112 region
        int pi = j >> 1, elem = j & 1;                 // pair index, element
        // find v: P[v] <= pi < P[v] + (v/2+1), P computed incrementally
        int v = 0, P = 0;
        while (P + (v / 2 + 1) <= pi) { P += v / 2 + 1; v++; }
        int u = 2 * (pi - P) + elem;
        if (u <= v) {
            int iuv = u * 256 + v * 16 + w, ivu = v * 256 + u * 16 + w;
            val = (u == v) ? A112 * w112[iuv] : A112 * (w112[iuv] + w112[ivu]);
        }                                              // else zero pad
    } else {
        int s = slot - 416;
        int u = s >> 4, v = s & 15;
        val = A101 * w101[u * 256 + v * 16 + w];
    }
    reinterpret_cast<float2*>(PW2)[idx] = make_float2(val, val);   // splat
}

// ---------- main kernel ----------
__global__ __launch_bounds__(T, 2) void e3nn_kernel(const float* __restrict__ feats,
                                                    const float* __restrict__ msgs,
                                                    float* __restrict__ out) {
    // SMEM (per CTA, ~46.5 KB):
    //   wbuf  : u64[2][672]   (10.5 KB)  per-w slab, double-buffered
    //   stage : float[9216]   (36 KB)    input staging (128 rows x 68 floats) /
    //                                    output staging (256 rows x 36 floats)
    extern __shared__ u64 sm[];
    u64* wbuf = sm;
    float* stageF = reinterpret_cast<float*>(sm + 1344);

    const int t = threadIdx.x;
    const long ctaBase = (long)blockIdx.x * NODES_PER_BLOCK;

    // ---- coalesced input staging: chunk A = nodes [ctaBase, +128) ----
    float xA[64], xB[64];
    {
        const float4* f4 = reinterpret_cast<const float4*>(feats) + ctaBase * 16;
        const float4* m4 = reinterpret_cast<const float4*>(msgs) + ctaBase * 16;
#pragma unroll
        for (int k = 0; k < 16; ++k) {
            int i = t + k * T;                 // 0..2047 over 128 nodes x 16 f4
            float4 a = f4[i], b = m4[i];
            float4 s = make_float4(a.x + b.x, a.y + b.y, a.z + b.z, a.w + b.w);
            int node = i >> 4, q = i & 15;
            *reinterpret_cast<float4*>(stageF + node * 68 + q * 4) = s;
        }
        __syncthreads();
#pragma unroll
        for (int q = 0; q < 16; ++q) {
            float4 vq = *reinterpret_cast<const float4*>(stageF + t * 68 + q * 4);
            xA[4 * q + 0] = vq.x; xA[4 * q + 1] = vq.y;
            xA[4 * q + 2] = vq.z; xA[4 * q + 3] = vq.w;
        }
        __syncthreads();
        // ---- chunk B = nodes [ctaBase+128, +256) ----
#pragma unroll
        for (int k = 0; k < 16; ++k) {
            int i = t + k * T;
            float4 a = f4[2048 + i], b = m4[2048 + i];
            float4 s = make_float4(a.x + b.x, a.y + b.y, a.z + b.z, a.w + b.w);
            int node = i >> 4, q = i & 15;
            *reinterpret_cast<float4*>(stageF + node * 68 + q * 4) = s;
        }
        __syncthreads();
#pragma unroll
        for (int q = 0; q < 16; ++q) {
            float4 vq = *reinterpret_cast<const float4*>(stageF + t * 68 + q * 4);
            xB[4 * q + 0] = vq.x; xB[4 * q + 1] = vq.y;
            xB[4 * q + 2] = vq.z; xB[4 * q + 3] = vq.w;
        }
    }

    // ---- pack node pair into f32x2 registers ----
    u64 px0[16];
    u64 px1[16][3];
#pragma unroll
    for (int v = 0; v < 16; ++v) px0[v] = fpack(xA[v], xB[v]);
#pragma unroll
    for (int v = 0; v < 16; ++v) {
#pragma unroll
        for (int i = 0; i < 3; ++i) px1[v][i] = fpack(xA[16 + 3 * v + i], xB[16 + 3 * v + i]);
    }

    // ---- cp.async weight staging: 672 u64 = 336 x 16B per slab ----
#define STAGE_SLAB(wi, buf)                                                               \
    do {                                                                                  \
        const u64* srcb = PW2 + (wi) * 672;                                               \
        u64* dstb = wbuf + (buf) * 672;                                                   \
        unsigned s0 = (unsigned)__cvta_generic_to_shared(dstb + 2 * t);                   \
        asm volatile("cp.async.cg.shared.global [%0], [%1], 16;" ::"r"(s0), "l"(srcb + 2 * t));   \
        asm volatile("cp.async.cg.shared.global [%0], [%1], 16;" ::"r"(s0 + 2048), "l"(srcb + 256 + 2 * t)); \
        if (t < 80) {                                                                     \
            asm volatile("cp.async.cg.shared.global [%0], [%1], 16;" ::"r"(s0 + 4096), "l"(srcb + 512 + 2 * t)); \
        }                                                                                 \
        asm volatile("cp.async.commit_group;");                                           \
    } while (0)

    STAGE_SLAB(0, 0);
    asm volatile("cp.async.wait_group 0;");
    __syncthreads();   // slab visible + input staging reads done before stage reuse

    const u64 CS2  = fpack(0.31622776601683794f, 0.31622776601683794f); // 1/sqrt(10)
    const u64 C62  = fpack(0.18257418583505536f, 0.18257418583505536f); // 1/sqrt(30)
    const u64 NEG1 = fpack(-1.0f, -1.0f);
    const u64 TWO2 = fpack(2.0f, 2.0f);

    // prefix of q112 pair-runs per v (in ull2 units)
    const int P16[16] = {0, 1, 2, 4, 6, 9, 12, 16, 20, 25, 30, 36, 42, 49, 56, 64};

#pragma unroll 1
    for (int w = 0; w < 16; ++w) {
        if (w < 15) STAGE_SLAB(w + 1, (w + 1) & 1);

        const u64* __restrict__ cw = wbuf + (w & 1) * 672;
        const ulonglong2* __restrict__ pairAB = reinterpret_cast<const ulonglong2*>(cw);
        const ulonglong2* __restrict__ q112p = reinterpret_cast<const ulonglong2*>(cw + 272);
        const u64* __restrict__ r101w = cw + 416;

        u64 acc00 = 0, acc01 = 0;
        u64 a10 = 0, a11 = 0, a12 = 0;
        u64 P0 = 0, P1 = 0, P2 = 0;
        u64 Q01 = 0, Q02 = 0, Q12 = 0;

        // ---- symmetric paths: triangular u <= v ----
#pragma unroll
        for (int v = 0; v < 16; ++v) {
            const int tb = v * (v + 1) / 2;
            const int np = v / 2 + 1;
            u64 s000 = 0;
            u64 s110_0 = 0, s110_1 = 0, s110_2 = 0;
            u64 s112_0 = 0, s112_1 = 0, s112_2 = 0;
#pragma unroll
            for (int g = 0; g < np; ++g) {
                const int u0 = 2 * g;
                ulonglong2 q2 = q112p[P16[v] + g];     // (q112[u0], q112[u0+1] or 0)
                ulonglong2 qab0 = pairAB[tb + u0];
                s000   = f2fma(qab0.x, px0[u0], s000);
                s110_0 = f2fma(qab0.y, px1[u0][0], s110_0);
                s110_1 = f2fma(qab0.y, px1[u0][1], s110_1);
                s110_2 = f2fma(qab0.y, px1[u0][2], s110_2);
                s112_0 = f2fma(q2.x, px1[u0][0], s112_0);
                s112_1 = f2fma(q2.x, px1[u0][1], s112_1);
                s112_2 = f2fma(q2.x, px1[u0][2], s112_2);
                if (u0 + 1 <= v) {
                    ulonglong2 qab1 = pairAB[tb + u0 + 1];
                    s000   = f2fma(qab1.x, px0[u0 + 1], s000);
                    s110_0 = f2fma(qab1.y, px1[u0 + 1][0], s110_0);
                    s110_1 = f2fma(qab1.y, px1[u0 + 1][1], s110_1);
                    s110_2 = f2fma(qab1.y, px1[u0 + 1][2], s110_2);
                    s112_0 = f2fma(q2.y, px1[u0 + 1][0], s112_0);
                    s112_1 = f2fma(q2.y, px1[u0 + 1][1], s112_1);
                    s112_2 = f2fma(q2.y, px1[u0 + 1][2], s112_2);
                }
            }
            // stage-2: register-direct (v static)
            acc00 = f2fma(s000, px0[v], acc00);
            acc01 = f2fma(s110_0, px1[v][0], acc01);
            acc01 = f2fma(s110_1, px1[v][1], acc01);
            acc01 = f2fma(s110_2, px1[v][2], acc01);

            P0 = f2fma(s112_0, px1[v][0], P0);
            P1 = f2fma(s112_1, px1[v][1], P1);
            P2 = f2fma(s112_2, px1[v][2], P2);
            Q01 = f2fma(s112_0, px1[v][1], Q01);
            Q01 = f2fma(s112_1, px1[v][0], Q01);
            Q02 = f2fma(s112_0, px1[v][2], Q02);
            Q02 = f2fma(s112_2, px1[v][0], Q02);
            Q12 = f2fma(s112_1, px1[v][2], Q12);
            Q12 = f2fma(s112_2, px1[v][1], Q12);
        }

        // ---- 101 path: r[u] = sum_v W101[u,v]*x0[v]; out1 += r[u] * x1[u] ----
#pragma unroll
        for (int u = 0; u < 16; ++u) {
            const ulonglong2* __restrict__ rw =
                reinterpret_cast<const ulonglong2*>(r101w + u * 16);
            u64 r = 0;
#pragma unroll
            for (int g = 0; g < 8; ++g) {
                ulonglong2 q = rw[g];
                r = f2fma(q.x, px0[2 * g + 0], r);
                r = f2fma(q.y, px0[2 * g + 1], r);
            }
            a10 = f2fma(r, px1[u][0], a10);
            a11 = f2fma(r, px1[u][1], a11);
            a12 = f2fma(r, px1[u][2], a12);
        }

        // ---- stage this w's 9 outputs per node into SMEM (group of 4 w's) ----
        {
            const int w2 = w & 3;
            float* sA = stageF + t * 36;
            float* sB = stageF + (t + T) * 36;
            float a, b;
            funpack(f2add(acc00, acc01), a, b);
            sA[w2] = a; sB[w2] = b;

            funpack(a10, a, b); sA[4 + 3 * w2 + 0] = a; sB[4 + 3 * w2 + 0] = b;
            funpack(a11, a, b); sA[4 + 3 * w2 + 1] = a; sB[4 + 3 * w2 + 1] = b;
            funpack(a12, a, b); sA[4 + 3 * w2 + 2] = a; sB[4 + 3 * w2 + 2] = b;

            funpack(f2mul(CS2, Q01), a, b); sA[16 + 5 * w2 + 0] = a; sB[16 + 5 * w2 + 0] = b;
            funpack(f2mul(CS2, Q02), a, b); sA[16 + 5 * w2 + 1] = a; sB[16 + 5 * w2 + 1] = b;
            funpack(f2mul(CS2, Q12), a, b); sA[16 + 5 * w2 + 2] = a; sB[16 + 5 * w2 + 2] = b;

            u64 d3 = f2fma(P1, NEG1, P0);                 // P0 - P1
            funpack(f2mul(CS2, d3), a, b); sA[16 + 5 * w2 + 3] = a; sB[16 + 5 * w2 + 3] = b;

            u64 s01 = f2add(P0, P1);
            u64 d4 = f2fma(TWO2, P2, f2mul(s01, NEG1));   // 2*P2 - P0 - P1
            funpack(f2mul(C62, d4), a, b); sA[16 + 5 * w2 + 4] = a; sB[16 + 5 * w2 + 4] = b;
        }

        // ---- every 4 w's: coalesced float4 flush of the staged group ----
        if ((w & 3) == 3) {
            __syncthreads();
            const int g = w >> 2;
            const float4* st4 = reinterpret_cast<const float4*>(stageF);  // [node][9 f4]
#pragma unroll 1
            for (int i = t; i < NODES_PER_BLOCK * 9; i += T) {
                int n = i / 9;
                int p = i - n * 9;
                float4 val = st4[i];
                int col = (p == 0) ? (4 * g)
                        : (p < 4)  ? (16 + 12 * g + 4 * (p - 1))
                                   : (64 + 20 * g + 4 * (p - 4));
                *reinterpret_cast<float4*>(out + (ctaBase + n) * 144 + col) = val;
            }
        }

        asm volatile("cp.async.wait_group 0;");
        __syncthreads();
    }
#undef STAGE_SLAB
}

extern "C" void kernel_launch(void* const* d_in, const int* in_sizes, int n_in,
                              void* d_out, int out_size) {
    const float* feats = (const float*)d_in[0];
    const float* msgs  = (const float*)d_in[1];
    const float* w000  = (const float*)d_in[2];
    const float* w101  = (const float*)d_in[3];
    const float* w110  = (const float*)d_in[4];
    const float* w112  = (const float*)d_in[5];
    float* out = (float*)d_out;

    // 2*672 u64 wbuf + 4608 u64 stage = 5952 u64 = 46.5 KB
    const int smem_bytes = (1344 + 4608) * (int)sizeof(u64);
    cudaFuncSetAttribute(e3nn_kernel, cudaFuncAttributeMaxDynamicSharedMemorySize, smem_bytes);

    prep_kernel<<<(16 * 672 + 255) / 256, 256>>>(w000, w101, w110, w112);
    e3nn_kernel<<<NNODES / NODES_PER_BLOCK, T, smem_bytes>>>(feats, msgs, out);
}

// round 12
// speedup vs baseline: 1.5028x; 1.5028x over previous
#include <cuda_runtime.h>

// E3nnSimpleNodeBlock: out = TensorSquare(feats+msgs), N=131072, MUL=16.
// Round 10: exact R8 champion (189us) + ONE change: empty asm memory fences at
// each unrolled inner-iteration boundary to cap ptxas LDS batching windows
// (theory: front-batched weight loads inflate live ranges -> 255 regs + spills).

#define T 128
#define NODES_PER_BLOCK 256
#define NNODES 131072

typedef unsigned long long u64;

// Per-w weight slab, splatted f32x2, pre-scaled. u64-indexed layout per w (664 u64):
//   [0,272)    : pairs (q000,q110) per triangular pair tri(v,u) -> ull2 at 2*tri
//   [272,408)  : q112 per triangular pair, u64 at 272+tri
//   [408,664)  : 101 weights W101[u][v] at 408 + u*16 + v
// PW2 = 16 slabs.
__device__ __align__(16) u64 PW2[16 * 664];

// ---------- f32x2 helpers ----------
__device__ __forceinline__ u64 f2fma(u64 a, u64 b, u64 c) {
    u64 d;
    asm("fma.rn.f32x2 %0, %1, %2, %3;" : "=l"(d) : "l"(a), "l"(b), "l"(c));
    return d;
}
__device__ __forceinline__ u64 f2add(u64 a, u64 b) {
    u64 d;
    asm("add.rn.f32x2 %0, %1, %2;" : "=l"(d) : "l"(a), "l"(b));
    return d;
}
__device__ __forceinline__ u64 f2mul(u64 a, u64 b) {
    u64 d;
    asm("mul.rn.f32x2 %0, %1, %2;" : "=l"(d) : "l"(a), "l"(b));
    return d;
}
__device__ __forceinline__ u64 fpack(float lo, float hi) {
    u64 d;
    asm("mov.b64 %0, {%1, %2};" : "=l"(d) : "f"(lo), "f"(hi));
    return d;
}
__device__ __forceinline__ void funpack(u64 p, float& lo, float& hi) {
    asm("mov.b64 {%0, %1}, %2;" : "=f"(lo), "=f"(hi) : "l"(p));
}
// compiler scheduling fence: caps LDS batching window, no codegen
__device__ __forceinline__ void sched_fence() { asm volatile("" ::: "memory"); }

// ---------- weight prep: symmetrize + scale + splat ----------
__global__ void prep_kernel(const float* __restrict__ w000, const float* __restrict__ w101,
                            const float* __restrict__ w110, const float* __restrict__ w112) {
    int idx = blockIdx.x * blockDim.x + threadIdx.x;   // 0 .. 16*664-1
    if (idx >= 16 * 664) return;
    int w = idx / 664;
    int slot = idx - w * 664;
    const float A000 = 0.04419417382415922f;           // sqrt(1/(2*MUL*MUL))
    const float A110 = 0.02551551815399144f;           // A000/sqrt(3)
    const float A101 = 0.0625f;                        // sqrt(3/MUL^2)/sqrt(3)
    const float A112 = 0.13975424859373686f;           // sqrt(5)/16

    float val;
    if (slot < 408) {
        int tri, comp;
        if (slot < 272) { tri = slot >> 1; comp = slot & 1; }
        else            { tri = slot - 272; comp = 2; }
        int v = 0;
        while ((v + 1) * (v + 2) / 2 <= tri) v++;
        int u = tri - v * (v + 1) / 2;
        int iuv = u * 256 + v * 16 + w;     // W[u][v][w]
        int ivu = v * 256 + u * 16 + w;     // W[v][u][w]
        const float* src = (comp == 0) ? w000 : (comp == 1) ? w110 : w112;
        float A = (comp == 0) ? A000 : (comp == 1) ? A110 : A112;
        val = (u == v) ? A * src[iuv] : A * (src[iuv] + src[ivu]);
    } else {
        int s = slot - 408;
        int u = s >> 4, v = s & 15;
        val = A101 * w101[u * 256 + v * 16 + w];
    }
    reinterpret_cast<float2*>(PW2)[idx] = make_float2(val, val);   // splat
}

// ---------- main kernel ----------
__global__ __launch_bounds__(T, 2) void e3nn_kernel(const float* __restrict__ feats,
                                                    const float* __restrict__ msgs,
                                                    float* __restrict__ out) {
    // SMEM (per CTA, ~47 KB):
    //   wbuf  : u64[2][672]     (10.5 KB)  per-w slab, double-buffered (664 used)
    //   stage : float[256*36]   (36 KB)    4-w-group output staging
    extern __shared__ u64 sm[];
    u64* wbuf = sm;                                           // 2*672 u64
    float* stage = reinterpret_cast<float*>(sm + 1344);       // 9216 floats

    const int t = threadIdx.x;
    const int nA = blockIdx.x * NODES_PER_BLOCK + t;
    const int nB = nA + T;

    // ---- load x = feats + msgs for both nodes, pack into f32x2 registers ----
    u64 px0[16];
    u64 px1[16][3];
    {
        float xA[64], xB[64];
        const float4* fA = reinterpret_cast<const float4*>(feats) + nA * 16;
        const float4* mA = reinterpret_cast<const float4*>(msgs) + nA * 16;
        const float4* fB = reinterpret_cast<const float4*>(feats) + nB * 16;
        const float4* mB = reinterpret_cast<const float4*>(msgs) + nB * 16;
#pragma unroll
        for (int q = 0; q < 16; ++q) {
            float4 f = fA[q], m = mA[q];
            xA[4 * q + 0] = f.x + m.x; xA[4 * q + 1] = f.y + m.y;
            xA[4 * q + 2] = f.z + m.z; xA[4 * q + 3] = f.w + m.w;
        }
#pragma unroll
        for (int q = 0; q < 16; ++q) {
            float4 f = fB[q], m = mB[q];
            xB[4 * q + 0] = f.x + m.x; xB[4 * q + 1] = f.y + m.y;
            xB[4 * q + 2] = f.z + m.z; xB[4 * q + 3] = f.w + m.w;
        }
#pragma unroll
        for (int v = 0; v < 16; ++v) px0[v] = fpack(xA[v], xB[v]);
#pragma unroll
        for (int v = 0; v < 16; ++v) {
#pragma unroll
            for (int i = 0; i < 3; ++i) px1[v][i] = fpack(xA[16 + 3 * v + i], xB[16 + 3 * v + i]);
        }
    }

    // ---- cp.async weight staging: 664 u64 = 332 x 16B chunks per slab ----
#define STAGE_SLAB(wi, buf)                                                               \
    do {                                                                                  \
        const u64* srcb = PW2 + (wi) * 664;                                               \
        u64* dstb = wbuf + (buf) * 672;                                                   \
        unsigned s0 = (unsigned)__cvta_generic_to_shared(dstb + 2 * t);                   \
        asm volatile("cp.async.cg.shared.global [%0], [%1], 16;" ::"r"(s0), "l"(srcb + 2 * t));   \
        asm volatile("cp.async.cg.shared.global [%0], [%1], 16;" ::"r"(s0 + 2048), "l"(srcb + 256 + 2 * t)); \
        if (t < 76) {                                                                     \
            asm volatile("cp.async.cg.shared.global [%0], [%1], 16;" ::"r"(s0 + 4096), "l"(srcb + 512 + 2 * t)); \
        }                                                                                 \
        asm volatile("cp.async.commit_group;");                                           \
    } while (0)

    STAGE_SLAB(0, 0);
    asm volatile("cp.async.wait_group 0;");
    __syncthreads();

    const u64 CS2  = fpack(0.31622776601683794f, 0.31622776601683794f); // 1/sqrt(10)
    const u64 C62  = fpack(0.18257418583505536f, 0.18257418583505536f); // 1/sqrt(30)
    const u64 NEG1 = fpack(-1.0f, -1.0f);
    const u64 TWO2 = fpack(2.0f, 2.0f);

#pragma unroll 1
    for (int w = 0; w < 16; ++w) {
        if (w < 15) STAGE_SLAB(w + 1, (w + 1) & 1);

        const u64* __restrict__ cw = wbuf + (w & 1) * 672;
        const ulonglong2* __restrict__ pairAB = reinterpret_cast<const ulonglong2*>(cw); // [tri]
        const u64* __restrict__ q112w = cw + 272;                                        // [tri]
        const u64* __restrict__ r101w = cw + 408;                                        // [u*16+v]

        u64 acc00 = 0, acc01 = 0;              // out0 paths (000 / 110)
        u64 a10 = 0, a11 = 0, a12 = 0;         // out1 k=0..2
        u64 P0 = 0, P1 = 0, P2 = 0;            // out2 diagonal sums
        u64 Q01 = 0, Q02 = 0, Q12 = 0;         // out2 cross sums

        // ---- symmetric paths: triangular u <= v, v static (full unroll) ----
#pragma unroll
        for (int v = 0; v < 16; ++v) {
            sched_fence();                      // cap LDS batching to this iteration
            const int tb = v * (v + 1) / 2;
            u64 s000 = 0;
            u64 s110_0 = 0, s110_1 = 0, s110_2 = 0;
            u64 s112_0 = 0, s112_1 = 0, s112_2 = 0;
#pragma unroll
            for (int u = 0; u <= v; ++u) {
                ulonglong2 qab = pairAB[tb + u];    // (q000, q110) broadcast LDS.128
                u64 q2 = q112w[tb + u];             // q112 broadcast LDS.64
                s000   = f2fma(qab.x, px0[u], s000);
                s110_0 = f2fma(qab.y, px1[u][0], s110_0);
                s110_1 = f2fma(qab.y, px1[u][1], s110_1);
                s110_2 = f2fma(qab.y, px1[u][2], s110_2);
                s112_0 = f2fma(q2, px1[u][0], s112_0);
                s112_1 = f2fma(q2, px1[u][1], s112_1);
                s112_2 = f2fma(q2, px1[u][2], s112_2);
            }
            // stage-2: register-direct (v static)
            acc00 = f2fma(s000, px0[v], acc00);
            acc01 = f2fma(s110_0, px1[v][0], acc01);
            acc01 = f2fma(s110_1, px1[v][1], acc01);
            acc01 = f2fma(s110_2, px1[v][2], acc01);

            P0 = f2fma(s112_0, px1[v][0], P0);
            P1 = f2fma(s112_1, px1[v][1], P1);
            P2 = f2fma(s112_2, px1[v][2], P2);
            Q01 = f2fma(s112_0, px1[v][1], Q01);
            Q01 = f2fma(s112_1, px1[v][0], Q01);
            Q02 = f2fma(s112_0, px1[v][2], Q02);
            Q02 = f2fma(s112_2, px1[v][0], Q02);
            Q12 = f2fma(s112_1, px1[v][2], Q12);
            Q12 = f2fma(s112_2, px1[v][1], Q12);
        }

        // ---- 101 path: r[u] = sum_v W101[u,v]*x0[v]; out1 += r[u] * x1[u] ----
#pragma unroll
        for (int u = 0; u < 16; ++u) {
            sched_fence();                      // cap LDS batching to this iteration
            const ulonglong2* __restrict__ rw =
                reinterpret_cast<const ulonglong2*>(r101w + u * 16);
            u64 r = 0;
#pragma unroll
            for (int g = 0; g < 8; ++g) {
                ulonglong2 q = rw[g];
                r = f2fma(q.x, px0[2 * g + 0], r);
                r = f2fma(q.y, px0[2 * g + 1], r);
            }
            a10 = f2fma(r, px1[u][0], a10);
            a11 = f2fma(r, px1[u][1], a11);
            a12 = f2fma(r, px1[u][2], a12);
        }

        // ---- stage this w's 9 outputs per node into SMEM (group of 4 w's) ----
        {
            const int w2 = w & 3;
            float* sA = stage + t * 36;
            float* sB = stage + (t + T) * 36;
            float a, b;
            funpack(f2add(acc00, acc01), a, b);
            sA[w2] = a; sB[w2] = b;

            funpack(a10, a, b); sA[4 + 3 * w2 + 0] = a; sB[4 + 3 * w2 + 0] = b;
            funpack(a11, a, b); sA[4 + 3 * w2 + 1] = a; sB[4 + 3 * w2 + 1] = b;
            funpack(a12, a, b); sA[4 + 3 * w2 + 2] = a; sB[4 + 3 * w2 + 2] = b;

            funpack(f2mul(CS2, Q01), a, b); sA[16 + 5 * w2 + 0] = a; sB[16 + 5 * w2 + 0] = b;
            funpack(f2mul(CS2, Q02), a, b); sA[16 + 5 * w2 + 1] = a; sB[16 + 5 * w2 + 1] = b;
            funpack(f2mul(CS2, Q12), a, b); sA[16 + 5 * w2 + 2] = a; sB[16 + 5 * w2 + 2] = b;

            u64 d3 = f2fma(P1, NEG1, P0);                 // P0 - P1
            funpack(f2mul(CS2, d3), a, b); sA[16 + 5 * w2 + 3] = a; sB[16 + 5 * w2 + 3] = b;

            u64 s01 = f2add(P0, P1);
            u64 d4 = f2fma(TWO2, P2, f2mul(s01, NEG1));   // 2*P2 - P0 - P1
            funpack(f2mul(C62, d4), a, b); sA[16 + 5 * w2 + 4] = a; sB[16 + 5 * w2 + 4] = b;
        }

        // ---- every 4 w's: coalesced float4 flush of the staged group ----
        if ((w & 3) == 3) {
            __syncthreads();
            const int g = w >> 2;
            const float4* st4 = reinterpret_cast<const float4*>(stage);  // [node][9 f4]
            const long ctaBase = (long)blockIdx.x * NODES_PER_BLOCK;
#pragma unroll 1
            for (int i = t; i < NODES_PER_BLOCK * 9; i += T) {
                int n = i / 9;
                int p = i - n * 9;
                float4 val = st4[i];
                int col = (p == 0) ? (4 * g)
                        : (p < 4)  ? (16 + 12 * g + 4 * (p - 1))
                                   : (64 + 20 * g + 4 * (p - 4));
                *reinterpret_cast<float4*>(out + (ctaBase + n) * 144 + col) = val;
            }
        }

        asm volatile("cp.async.wait_group 0;");
        __syncthreads();
    }
#undef STAGE_SLAB
}

extern "C" void kernel_launch(void* const* d_in, const int* in_sizes, int n_in,
                              void* d_out, int out_size) {
    const float* feats = (const float*)d_in[0];
    const float* msgs  = (const float*)d_in[1];
    const float* w000  = (const float*)d_in[2];
    const float* w101  = (const float*)d_in[3];
    const float* w110  = (const float*)d_in[4];
    const float* w112  = (const float*)d_in[5];
    float* out = (float*)d_out;

    // 2*672 u64 wbuf + 4608 u64 stage = 5952 u64 = 46.5 KB
    const int smem_bytes = (1344 + 4608) * (int)sizeof(u64);
    cudaFuncSetAttribute(e3nn_kernel, cudaFuncAttributeMaxDynamicSharedMemorySize, smem_bytes);

    prep_kernel<<<(16 * 664 + 255) / 256, 256>>>(w000, w101, w110, w112);
    e3nn_kernel<<<NNODES / NODES_PER_BLOCK, T, smem_bytes>>>(feats, msgs, out);
}

// round 13
// speedup vs baseline: 1.5750x; 1.0481x over previous
#include <cuda_runtime.h>

// E3nnSimpleNodeBlock: out = TensorSquare(feats+msgs), N=131072, MUL=16.
// Round 12: SCALAR f32, ONE node per thread. Key insight: FFMA and FFMA2 have the
// same issue rate (rt=2), so f32x2 node-pair packing bought no throughput -- only
// 2x register pressure (the root cause of persistent 255-reg spills). Same folded
// algorithm (triangular sym paths + refactored 101), same double-buffered per-w
// slab + staged float4 output flush + sched fences. 128-reg cap -> 4 CTAs/SM.

#define T 128
#define NODES_PER_BLOCK 128   // 1 node per thread
#define NNODES 131072

// Per-w weight slab, scalar f32, pre-scaled (672 floats per w, 664 used):
//   [0,272)   : pairs (q000,q110) per triangular pair -> float2 at [tri]
//   [272,408) : q112 per triangular pair (float)
//   [408,664) : 101 weights W101[u][v] at 408 + u*16 + v
__device__ __align__(16) float PW[16 * 672];

// compiler scheduling fence: caps LDS batching window, no codegen
__device__ __forceinline__ void sched_fence() { asm volatile("" ::: "memory"); }

// ---------- weight prep: symmetrize + scale ----------
__global__ void prep_kernel(const float* __restrict__ w000, const float* __restrict__ w101,
                            const float* __restrict__ w110, const float* __restrict__ w112) {
    int idx = blockIdx.x * blockDim.x + threadIdx.x;   // 0 .. 16*672-1
    if (idx >= 16 * 672) return;
    int w = idx / 672;
    int slot = idx - w * 672;
    const float A000 = 0.04419417382415922f;           // sqrt(1/(2*MUL*MUL))
    const float A110 = 0.02551551815399144f;           // A000/sqrt(3)
    const float A101 = 0.0625f;                        // sqrt(3/MUL^2)/sqrt(3)
    const float A112 = 0.13975424859373686f;           // sqrt(5)/16

    float val = 0.0f;
    if (slot < 408) {
        int tri, comp;
        if (slot < 272) { tri = slot >> 1; comp = slot & 1; }   // 0 -> q000, 1 -> q110
        else            { tri = slot - 272; comp = 2; }         // q112
        int v = 0;
        while ((v + 1) * (v + 2) / 2 <= tri) v++;
        int u = tri - v * (v + 1) / 2;
        int iuv = u * 256 + v * 16 + w;     // W[u][v][w]
        int ivu = v * 256 + u * 16 + w;     // W[v][u][w]
        const float* src = (comp == 0) ? w000 : (comp == 1) ? w110 : w112;
        float A = (comp == 0) ? A000 : (comp == 1) ? A110 : A112;
        val = (u == v) ? A * src[iuv] : A * (src[iuv] + src[ivu]);
    } else if (slot < 664) {
        int s = slot - 408;
        int u = s >> 4, v = s & 15;
        val = A101 * w101[u * 256 + v * 16 + w];
    }
    PW[idx] = val;
}

// ---------- main kernel ----------
__global__ __launch_bounds__(T, 4) void e3nn_kernel(const float* __restrict__ feats,
                                                    const float* __restrict__ msgs,
                                                    float* __restrict__ out) {
    // SMEM (per CTA, ~23.8 KB):
    //   wbuf  : float[2][672]   (5.25 KB)  per-w slab, double-buffered
    //   stage : float[128*36]   (18 KB)    4-w-group output staging
    __shared__ __align__(16) float wbuf[2][672];
    __shared__ __align__(16) float stage[NODES_PER_BLOCK * 36];

    const int t = threadIdx.x;
    const long node = (long)blockIdx.x * NODES_PER_BLOCK + t;

    // ---- load x = feats + msgs for this node ----
    float x0[16];
    float x1[16][3];
    {
        float xA[64];
        const float4* fA = reinterpret_cast<const float4*>(feats) + node * 16;
        const float4* mA = reinterpret_cast<const float4*>(msgs) + node * 16;
#pragma unroll
        for (int q = 0; q < 16; ++q) {
            float4 f = fA[q], m = mA[q];
            xA[4 * q + 0] = f.x + m.x; xA[4 * q + 1] = f.y + m.y;
            xA[4 * q + 2] = f.z + m.z; xA[4 * q + 3] = f.w + m.w;
        }
#pragma unroll
        for (int v = 0; v < 16; ++v) x0[v] = xA[v];
#pragma unroll
        for (int v = 0; v < 16; ++v) {
#pragma unroll
            for (int i = 0; i < 3; ++i) x1[v][i] = xA[16 + 3 * v + i];
        }
    }

    // ---- cp.async weight staging: 672 floats = 168 x 16B chunks per slab ----
#define STAGE_SLAB(wi, buf)                                                               \
    do {                                                                                  \
        const float* srcb = PW + (wi) * 672;                                              \
        float* dstb = wbuf[(buf)];                                                        \
        unsigned s0 = (unsigned)__cvta_generic_to_shared(dstb + 4 * t);                   \
        asm volatile("cp.async.cg.shared.global [%0], [%1], 16;" ::"r"(s0), "l"(srcb + 4 * t)); \
        if (t < 40) {                                                                     \
            asm volatile("cp.async.cg.shared.global [%0], [%1], 16;" ::"r"(s0 + 2048), "l"(srcb + 512 + 4 * t)); \
        }                                                                                 \
        asm volatile("cp.async.commit_group;");                                           \
    } while (0)

    STAGE_SLAB(0, 0);
    asm volatile("cp.async.wait_group 0;");
    __syncthreads();

    const float CS2 = 0.31622776601683794f;   // 1/sqrt(10)
    const float C62 = 0.18257418583505536f;   // 1/sqrt(30)

#pragma unroll 1
    for (int w = 0; w < 16; ++w) {
        if (w < 15) STAGE_SLAB(w + 1, (w + 1) & 1);

        const float* __restrict__ cw = wbuf[w & 1];
        const float2* __restrict__ pairAB = reinterpret_cast<const float2*>(cw);  // [tri]
        const float* __restrict__ q112w = cw + 272;                               // [tri]
        const float* __restrict__ r101w = cw + 408;                               // [u*16+v]

        float acc00 = 0.f, acc01 = 0.f;            // out0 paths (000 / 110)
        float a10 = 0.f, a11 = 0.f, a12 = 0.f;     // out1 k=0..2
        float P0 = 0.f, P1 = 0.f, P2 = 0.f;        // out2 diagonal sums
        float Q01 = 0.f, Q02 = 0.f, Q12 = 0.f;     // out2 cross sums

        // ---- symmetric paths: triangular u <= v, v static (full unroll) ----
#pragma unroll
        for (int v = 0; v < 16; ++v) {
            sched_fence();                          // cap LDS batching to this iteration
            const int tb = v * (v + 1) / 2;
            float s000 = 0.f;
            float s110_0 = 0.f, s110_1 = 0.f, s110_2 = 0.f;
            float s112_0 = 0.f, s112_1 = 0.f, s112_2 = 0.f;
#pragma unroll
            for (int u = 0; u <= v; ++u) {
                float2 qab = pairAB[tb + u];        // (q000, q110) broadcast LDS.64
                float q2 = q112w[tb + u];           // q112 broadcast LDS.32
                s000   = fmaf(qab.x, x0[u], s000);
                s110_0 = fmaf(qab.y, x1[u][0], s110_0);
                s110_1 = fmaf(qab.y, x1[u][1], s110_1);
                s110_2 = fmaf(qab.y, x1[u][2], s110_2);
                s112_0 = fmaf(q2, x1[u][0], s112_0);
                s112_1 = fmaf(q2, x1[u][1], s112_1);
                s112_2 = fmaf(q2, x1[u][2], s112_2);
            }
            // stage-2: register-direct (v static)
            acc00 = fmaf(s000, x0[v], acc00);
            acc01 = fmaf(s110_0, x1[v][0], acc01);
            acc01 = fmaf(s110_1, x1[v][1], acc01);
            acc01 = fmaf(s110_2, x1[v][2], acc01);

            P0 = fmaf(s112_0, x1[v][0], P0);
            P1 = fmaf(s112_1, x1[v][1], P1);
            P2 = fmaf(s112_2, x1[v][2], P2);
            Q01 = fmaf(s112_0, x1[v][1], Q01);
            Q01 = fmaf(s112_1, x1[v][0], Q01);
            Q02 = fmaf(s112_0, x1[v][2], Q02);
            Q02 = fmaf(s112_2, x1[v][0], Q02);
            Q12 = fmaf(s112_1, x1[v][2], Q12);
            Q12 = fmaf(s112_2, x1[v][1], Q12);
        }

        // ---- 101 path: r[u] = sum_v W101[u,v]*x0[v]; out1 += r[u] * x1[u] ----
#pragma unroll
        for (int u = 0; u < 16; ++u) {
            sched_fence();                          // cap LDS batching to this iteration
            const float2* __restrict__ rw = reinterpret_cast<const float2*>(r101w + u * 16);
            float r = 0.f;
#pragma unroll
            for (int g = 0; g < 8; ++g) {
                float2 q = rw[g];                   // LDS.64 broadcast
                r = fmaf(q.x, x0[2 * g + 0], r);
                r = fmaf(q.y, x0[2 * g + 1], r);
            }
            a10 = fmaf(r, x1[u][0], a10);
            a11 = fmaf(r, x1[u][1], a11);
            a12 = fmaf(r, x1[u][2], a12);
        }

        // ---- stage this w's 9 outputs into SMEM (group of 4 w's) ----
        {
            const int w2 = w & 3;
            float* sA = stage + t * 36;
            sA[w2] = acc00 + acc01;

            sA[4 + 3 * w2 + 0] = a10;
            sA[4 + 3 * w2 + 1] = a11;
            sA[4 + 3 * w2 + 2] = a12;

            sA[16 + 5 * w2 + 0] = CS2 * Q01;
            sA[16 + 5 * w2 + 1] = CS2 * Q02;
            sA[16 + 5 * w2 + 2] = CS2 * Q12;
            sA[16 + 5 * w2 + 3] = CS2 * (P0 - P1);
            sA[16 + 5 * w2 + 4] = C62 * (2.0f * P2 - P0 - P1);
        }

        // ---- every 4 w's: coalesced float4 flush of the staged group ----
        if ((w & 3) == 3) {
            __syncthreads();
            const int g = w >> 2;
            const float4* st4 = reinterpret_cast<const float4*>(stage);  // [node][9 f4]
            const long ctaBase = (long)blockIdx.x * NODES_PER_BLOCK;
#pragma unroll
            for (int k = 0; k < 9; ++k) {
                int i = t + k * T;                  // 0 .. 128*9-1
                int n = i / 9;
                int p = i - n * 9;
                float4 val = st4[i];
                int col = (p == 0) ? (4 * g)
                        : (p < 4)  ? (16 + 12 * g + 4 * (p - 1))
                                   : (64 + 20 * g + 4 * (p - 4));
                *reinterpret_cast<float4*>(out + (ctaBase + n) * 144 + col) = val;
            }
        }

        asm volatile("cp.async.wait_group 0;");
        __syncthreads();
    }
#undef STAGE_SLAB
}

extern "C" void kernel_launch(void* const* d_in, const int* in_sizes, int n_in,
                              void* d_out, int out_size) {
    const float* feats = (const float*)d_in[0];
    const float* msgs  = (const float*)d_in[1];
    const float* w000  = (const float*)d_in[2];
    const float* w101  = (const float*)d_in[3];
    const float* w110  = (const float*)d_in[4];
    const float* w112  = (const float*)d_in[5];
    float* out = (float*)d_out;

    prep_kernel<<<(16 * 672 + 255) / 256, 256>>>(w000, w101, w110, w112);
    e3nn_kernel<<<NNODES / NODES_PER_BLOCK, T>>>(feats, msgs, out);
}